// round 1
// baseline (speedup 1.0000x reference)
#include <cuda_runtime.h>
#include <cstdint>

#define BN     50000
#define NBR    4
#define DD     32
#define CC     128          // NBR*DD
#define MM     256
#define NODES  (BN + MM)    // 50256
#define MD     (MM * DD)    // 8192

// scratch (static device globals — no allocation)
__device__ float g_h[(size_t)NODES * CC];
__device__ float g_out[(size_t)NODES * CC];

// ---------------------------------------------------------------------------
// vector reduction to global memory: red.global.add.v4.f32 (sm_90+)
// ---------------------------------------------------------------------------
__device__ __forceinline__ void red_add_v4(float* addr, float4 v) {
    asm volatile("red.global.add.v4.f32 [%0], {%1, %2, %3, %4};"
                 :: "l"(addr), "f"(v.x), "f"(v.y), "f"(v.z), "f"(v.w)
                 : "memory");
}

// ---------------------------------------------------------------------------
// Kernel 1: h[node, b*32+e] = sum_d Xin[node, b*32+d] * W_conv[b, d, e]
//   node < BN : Xin row = X_B row
//   node >= BN: Xin row = codebook[b, node-BN, :] * wr
// One warp handles (32 rows, 1 branch); lane = row within group.
// ---------------------------------------------------------------------------
__global__ void compute_h_kernel(const float* __restrict__ X,
                                 const float* __restrict__ codebook,
                                 const float* __restrict__ W_conv,
                                 const float* __restrict__ wr_p) {
    __shared__ float Ws[NBR * DD * DD];   // 16KB
    for (int i = threadIdx.x; i < NBR * DD * DD; i += blockDim.x)
        Ws[i] = W_conv[i];
    __syncthreads();

    const float wr = wr_p[0];
    const int gw   = (blockIdx.x * blockDim.x + threadIdx.x) >> 5;
    const int lane = threadIdx.x & 31;
    const int b    = gw & 3;
    const int row  = (gw >> 2) * 32 + lane;
    if (row >= NODES) return;

    float x[DD];
    if (row < BN) {
        const float4* p = (const float4*)(X + (size_t)row * CC + b * DD);
        #pragma unroll
        for (int i = 0; i < 8; i++) {
            float4 v = p[i];
            x[4*i+0] = v.x; x[4*i+1] = v.y; x[4*i+2] = v.z; x[4*i+3] = v.w;
        }
    } else {
        const int m = row - BN;
        const float4* p = (const float4*)(codebook + ((size_t)b * MM + m) * DD);
        #pragma unroll
        for (int i = 0; i < 8; i++) {
            float4 v = p[i];
            x[4*i+0] = v.x * wr; x[4*i+1] = v.y * wr;
            x[4*i+2] = v.z * wr; x[4*i+3] = v.w * wr;
        }
    }

    float acc[DD];
    #pragma unroll
    for (int e = 0; e < DD; e++) acc[e] = 0.0f;

    #pragma unroll
    for (int d = 0; d < DD; d++) {
        const float xd = x[d];
        const float* wrow = &Ws[b * (DD*DD) + d * DD];
        #pragma unroll
        for (int e = 0; e < DD; e++)
            acc[e] = fmaf(xd, wrow[e], acc[e]);
    }

    float4* o = (float4*)(g_h + (size_t)row * CC + b * DD);
    #pragma unroll
    for (int i = 0; i < 8; i++)
        o[i] = make_float4(acc[4*i+0], acc[4*i+1], acc[4*i+2], acc[4*i+3]);
}

// ---------------------------------------------------------------------------
// Kernel 2: init out[node, c] = b_conv[c]  (b_conv flat [NB*D] == column order)
// ---------------------------------------------------------------------------
__global__ void init_out_kernel(const float* __restrict__ b_conv) {
    const int total4 = NODES * CC / 4;
    int idx = blockIdx.x * blockDim.x + threadIdx.x;
    if (idx >= total4) return;
    float4 v = ((const float4*)b_conv)[idx & 31];   // 32 float4 per row
    ((float4*)g_out)[idx] = v;
}

// ---------------------------------------------------------------------------
// Kernel 3: intra-batch scatter.  One warp per edge, lane covers 4 columns.
//   out[dst] += w * h[src]
// ---------------------------------------------------------------------------
__global__ void scatter_bb_kernel(const int* __restrict__ src,
                                  const int* __restrict__ dst,
                                  const float* __restrict__ w, int E) {
    const int gw   = (blockIdx.x * blockDim.x + threadIdx.x) >> 5;
    const int lane = threadIdx.x & 31;
    if (gw >= E) return;
    const int s = src[gw];
    const int d = dst[gw];
    const float we = w[gw];
    float4 hv = ((const float4*)(g_h + (size_t)s * CC))[lane];
    hv.x *= we; hv.y *= we; hv.z *= we; hv.w *= we;
    red_add_v4(g_out + (size_t)d * CC + lane * 4, hv);
}

// ---------------------------------------------------------------------------
// Kernel 4: cross edges.  s = BN + c_indices[src_bm], d = dst_bm.
//   out[d] += w * h[s]   (BM block)
//   out[s] += w * h[d]   (MB block)
// ---------------------------------------------------------------------------
__global__ void scatter_bm_kernel(const int* __restrict__ src,
                                  const int* __restrict__ dst,
                                  const float* __restrict__ w,
                                  const int* __restrict__ c_idx, int E) {
    const int gw   = (blockIdx.x * blockDim.x + threadIdx.x) >> 5;
    const int lane = threadIdx.x & 31;
    if (gw >= E) return;
    const int d = dst[gw];
    const int s = BN + c_idx[src[gw]];
    const float we = w[gw];

    float4 hs = ((const float4*)(g_h + (size_t)s * CC))[lane];
    hs.x *= we; hs.y *= we; hs.z *= we; hs.w *= we;
    red_add_v4(g_out + (size_t)d * CC + lane * 4, hs);

    float4 hd = ((const float4*)(g_h + (size_t)d * CC))[lane];
    hd.x *= we; hd.y *= we; hd.z *= we; hd.w *= we;
    red_add_v4(g_out + (size_t)s * CC + lane * 4, hd);
}

// ---------------------------------------------------------------------------
// Kernel 5: info_backward = wr * sum_{b,m,e} out[BN+m, b*32+e] * vq_grad[b,m,e]
// ---------------------------------------------------------------------------
__global__ void info_kernel(const float* __restrict__ vq_grad,
                            const float* __restrict__ wr_p,
                            float* __restrict__ out_scalar) {
    __shared__ float red[256];
    float s = 0.0f;
    for (int idx = threadIdx.x; idx < NBR * MD; idx += 256) {
        const int b = idx >> 13;        // / (M*D)
        const int r = idx & (MD - 1);
        const int m = r >> 5;
        const int e = r & 31;
        s += g_out[(size_t)(BN + m) * CC + b * DD + e] * vq_grad[idx];
    }
    red[threadIdx.x] = s;
    __syncthreads();
    for (int st = 128; st > 0; st >>= 1) {
        if (threadIdx.x < st) red[threadIdx.x] += red[threadIdx.x + st];
        __syncthreads();
    }
    if (threadIdx.x == 0) *out_scalar = red[0] * wr_p[0];
}

// ---------------------------------------------------------------------------
// Kernel 6: Y[r,c] = sum_k out[r,k]*W_fc[k,c] + b_fc[c] + X_B[r,c]
// Block = 16 rows. 256 threads: thread (rg = tid>>5, cg = tid&31) computes
// rows {2rg, 2rg+1} x cols {4cg..4cg+3}. W loaded as float4 (coalesced),
// Xs reads are warp-uniform broadcasts.
// ---------------------------------------------------------------------------
__global__ void y_kernel(const float* __restrict__ X,
                         const float* __restrict__ W_fc,
                         const float* __restrict__ b_fc,
                         float* __restrict__ Y) {
    __shared__ float Xs[16][CC];
    const int row0 = blockIdx.x * 16;
    for (int i = threadIdx.x; i < 16 * CC; i += 256) {
        const int r = i >> 7, c = i & 127;
        Xs[r][c] = g_out[(size_t)(row0 + r) * CC + c];
    }
    __syncthreads();

    const int cg = threadIdx.x & 31;   // column group (4 cols)
    const int rg = threadIdx.x >> 5;   // row group   (2 rows)
    const float4* W4 = (const float4*)W_fc;   // [k][32] float4 per row of W

    float4 acc0 = make_float4(0.f, 0.f, 0.f, 0.f);
    float4 acc1 = make_float4(0.f, 0.f, 0.f, 0.f);

    #pragma unroll 4
    for (int k = 0; k < CC; k++) {
        const float4 wv = W4[k * 32 + cg];
        const float x0 = Xs[rg * 2 + 0][k];
        const float x1 = Xs[rg * 2 + 1][k];
        acc0.x = fmaf(x0, wv.x, acc0.x); acc0.y = fmaf(x0, wv.y, acc0.y);
        acc0.z = fmaf(x0, wv.z, acc0.z); acc0.w = fmaf(x0, wv.w, acc0.w);
        acc1.x = fmaf(x1, wv.x, acc1.x); acc1.y = fmaf(x1, wv.y, acc1.y);
        acc1.z = fmaf(x1, wv.z, acc1.z); acc1.w = fmaf(x1, wv.w, acc1.w);
    }

    const float4 bf = ((const float4*)b_fc)[cg];
    {
        const int row = row0 + rg * 2;
        const float4 xb = ((const float4*)(X + (size_t)row * CC))[cg];
        float4 o = make_float4(acc0.x + bf.x + xb.x, acc0.y + bf.y + xb.y,
                               acc0.z + bf.z + xb.z, acc0.w + bf.w + xb.w);
        ((float4*)(Y + (size_t)row * CC))[cg] = o;
    }
    {
        const int row = row0 + rg * 2 + 1;
        const float4 xb = ((const float4*)(X + (size_t)row * CC))[cg];
        float4 o = make_float4(acc1.x + bf.x + xb.x, acc1.y + bf.y + xb.y,
                               acc1.z + bf.z + xb.z, acc1.w + bf.w + xb.w);
        ((float4*)(Y + (size_t)row * CC))[cg] = o;
    }
}

// ---------------------------------------------------------------------------
extern "C" void kernel_launch(void* const* d_in, const int* in_sizes, int n_in,
                              void* d_out, int out_size) {
    const float* X_B      = (const float*)d_in[0];
    const int*   esrc_bb  = (const int*)  d_in[1];
    const int*   edst_bb  = (const int*)  d_in[2];
    const float* ew_bb    = (const float*)d_in[3];
    const int*   esrc_bm  = (const int*)  d_in[4];
    const int*   edst_bm  = (const int*)  d_in[5];
    const float* ew_bm    = (const float*)d_in[6];
    const int*   c_idx    = (const int*)  d_in[7];
    const float* wr       = (const float*)d_in[8];
    const float* codebook = (const float*)d_in[9];
    const float* vq_grad  = (const float*)d_in[10];
    const float* W_conv   = (const float*)d_in[11];
    // b_conv = d_in[12], W_fc = d_in[13], b_fc = d_in[14]
    const float* b_conv   = (const float*)d_in[12];
    const float* W_fc     = (const float*)d_in[13];
    const float* b_fc     = (const float*)d_in[14];
    float* out = (float*)d_out;

    const int E = in_sizes[1];

    // h = Xin @ blockdiag(W_conv): one warp per (32 rows, branch)
    {
        const int warps  = ((NODES + 31) / 32) * NBR;
        const int blocks = (warps * 32 + 255) / 256;
        compute_h_kernel<<<blocks, 256>>>(X_B, codebook, W_conv, wr);
    }
    // out = broadcast(b_conv)
    {
        const int total4 = NODES * CC / 4;
        init_out_kernel<<<(total4 + 255) / 256, 256>>>(b_conv);
    }
    // scatter: warp per edge
    scatter_bb_kernel<<<(E + 7) / 8, 256>>>(esrc_bb, edst_bb, ew_bb, E);
    scatter_bm_kernel<<<(E + 7) / 8, 256>>>(esrc_bm, edst_bm, ew_bm, c_idx, E);
    // info_backward scalar -> last output element
    info_kernel<<<1, 256>>>(vq_grad, wr, out + (out_size - 1));
    // Y = out[:B] @ W_fc + b_fc + X_B
    y_kernel<<<BN / 16, 256>>>(X_B, W_fc, b_fc, out);
}

// round 2
// speedup vs baseline: 1.3361x; 1.3361x over previous
#include <cuda_runtime.h>
#include <cstdint>

#define BN     50000
#define NBR    4
#define DD     32
#define CC     128          // NBR*DD
#define MM     256
#define NODES  (BN + MM)    // 50256
#define MD     (MM * DD)    // 8192
#define CAPR   128          // per-batch-row bucket capacity (mean ~40)
#define CAPM   4608         // per-codeword bucket capacity (mean ~3900)

// scratch (static device globals — no allocation)
__device__ float g_h[(size_t)NODES * CC];
__device__ float g_out[(size_t)BN * CC];
__device__ int   g_cnt[BN];
__device__ int   g_ccnt[MM];
__device__ int2  g_ent[(size_t)BN * CAPR];    // (src_row, w) per batch-dst
__device__ int2  g_ment[(size_t)MM * CAPM];   // (dst_row, w) per codeword
__device__ float g_macc[MM * CC];             // codeword-row MB accumulator

__device__ __forceinline__ void red_add_v4(float* addr, float4 v) {
    asm volatile("red.global.add.v4.f32 [%0], {%1, %2, %3, %4};"
                 :: "l"(addr), "f"(v.x), "f"(v.y), "f"(v.z), "f"(v.w)
                 : "memory");
}

// ---------------------------------------------------------------------------
// Zero counters + macc
// ---------------------------------------------------------------------------
__global__ void zero_kernel() {
    const int idx = blockIdx.x * blockDim.x + threadIdx.x;
    if (idx < BN) g_cnt[idx] = 0;
    else if (idx < BN + MM) g_ccnt[idx - BN] = 0;
    else if (idx < BN + MM + MM * CC) g_macc[idx - BN - MM] = 0.0f;
}

// ---------------------------------------------------------------------------
// h[node, b*32+e] = sum_d Xin[node, b*32+d] * W_conv[b, d, e]
// One warp = (32 rows, 1 branch).
// ---------------------------------------------------------------------------
__global__ void compute_h_kernel(const float* __restrict__ X,
                                 const float* __restrict__ codebook,
                                 const float* __restrict__ W_conv,
                                 const float* __restrict__ wr_p) {
    __shared__ float Ws[NBR * DD * DD];   // 16KB
    for (int i = threadIdx.x; i < NBR * DD * DD; i += blockDim.x)
        Ws[i] = W_conv[i];
    __syncthreads();

    const float wr = wr_p[0];
    const int gw   = (blockIdx.x * blockDim.x + threadIdx.x) >> 5;
    const int lane = threadIdx.x & 31;
    const int b    = gw & 3;
    const int row  = (gw >> 2) * 32 + lane;
    if (row >= NODES) return;

    float x[DD];
    if (row < BN) {
        const float4* p = (const float4*)(X + (size_t)row * CC + b * DD);
        #pragma unroll
        for (int i = 0; i < 8; i++) {
            float4 v = p[i];
            x[4*i+0] = v.x; x[4*i+1] = v.y; x[4*i+2] = v.z; x[4*i+3] = v.w;
        }
    } else {
        const int m = row - BN;
        const float4* p = (const float4*)(codebook + ((size_t)b * MM + m) * DD);
        #pragma unroll
        for (int i = 0; i < 8; i++) {
            float4 v = p[i];
            x[4*i+0] = v.x * wr; x[4*i+1] = v.y * wr;
            x[4*i+2] = v.z * wr; x[4*i+3] = v.w * wr;
        }
    }

    float acc[DD];
    #pragma unroll
    for (int e = 0; e < DD; e++) acc[e] = 0.0f;
    #pragma unroll
    for (int d = 0; d < DD; d++) {
        const float xd = x[d];
        const float* wrow = &Ws[b * (DD*DD) + d * DD];
        #pragma unroll
        for (int e = 0; e < DD; e++)
            acc[e] = fmaf(xd, wrow[e], acc[e]);
    }

    float4* o = (float4*)(g_h + (size_t)row * CC + b * DD);
    #pragma unroll
    for (int i = 0; i < 8; i++)
        o[i] = make_float4(acc[4*i+0], acc[4*i+1], acc[4*i+2], acc[4*i+3]);
}

// ---------------------------------------------------------------------------
// Bucket all edges by destination batch row (bb + bm streams).
// Entry = (src_row, weight); src_row for bm edges remapped to codeword row.
// ---------------------------------------------------------------------------
__global__ void fill_dst_kernel(const int* __restrict__ sbb, const int* __restrict__ dbb,
                                const float* __restrict__ wbb,
                                const int* __restrict__ sbm, const int* __restrict__ dbm,
                                const float* __restrict__ wbm,
                                const int* __restrict__ cidx, int Ebb, int Etot) {
    const int i = blockIdx.x * blockDim.x + threadIdx.x;
    if (i >= Etot) return;
    int r, s; float w;
    if (i < Ebb) { r = dbb[i]; s = sbb[i]; w = wbb[i]; }
    else { const int j = i - Ebb; r = dbm[j]; s = BN + cidx[sbm[j]]; w = wbm[j]; }
    const int pos = atomicAdd(&g_cnt[r], 1);
    if (pos < CAPR)
        g_ent[(size_t)r * CAPR + pos] = make_int2(s, __float_as_int(w));
}

// ---------------------------------------------------------------------------
// Bucket bm edges by codeword (smem-privatized tickets to dodge the
// 3900-deep per-address global atomic chains on 256 counters).
// ---------------------------------------------------------------------------
#define EPT 8
__global__ void mb_fill_kernel(const int* __restrict__ sbm, const int* __restrict__ dbm,
                               const float* __restrict__ wbm,
                               const int* __restrict__ cidx, int E) {
    __shared__ int lc[MM];
    __shared__ int lbase[MM];
    const int tid = threadIdx.x;      // 256 threads
    lc[tid] = 0;
    __syncthreads();

    const int base = blockIdx.x * (256 * EPT);
    int myc[EPT], myl[EPT], myd[EPT]; float myw[EPT];
    #pragma unroll
    for (int k = 0; k < EPT; k++) {
        const int i = base + k * 256 + tid;
        if (i < E) {
            const int c = cidx[sbm[i]];
            myc[k] = c;
            myd[k] = dbm[i];
            myw[k] = wbm[i];
            myl[k] = atomicAdd(&lc[c], 1);
        } else myc[k] = -1;
    }
    __syncthreads();
    lbase[tid] = (lc[tid] > 0) ? atomicAdd(&g_ccnt[tid], lc[tid]) : 0;
    __syncthreads();
    #pragma unroll
    for (int k = 0; k < EPT; k++) {
        if (myc[k] >= 0) {
            const int pos = lbase[myc[k]] + myl[k];
            if (pos < CAPM)
                g_ment[(size_t)myc[k] * CAPM + pos] =
                    make_int2(myd[k], __float_as_int(myw[k]));
        }
    }
}

// ---------------------------------------------------------------------------
// Gather: one warp per batch row.  out[r] = b_conv + sum w * h[src].
// Zero atomics; each out row written exactly once.
// ---------------------------------------------------------------------------
__global__ void gather_kernel(const float* __restrict__ b_conv) {
    const int gw   = (blockIdx.x * blockDim.x + threadIdx.x) >> 5;
    const int lane = threadIdx.x & 31;
    if (gw >= BN) return;
    int n = g_cnt[gw]; if (n > CAPR) n = CAPR;

    float4 acc = ((const float4*)b_conv)[lane];
    const int2* ep = g_ent + (size_t)gw * CAPR;

    int2 nxt = (n > 0) ? ep[0] : make_int2(0, 0);
    for (int e = 0; e < n; e++) {
        const int2 cur = nxt;
        if (e + 1 < n) nxt = ep[e + 1];
        const float w = __int_as_float(cur.y);
        const float4 hv = ((const float4*)(g_h + (size_t)cur.x * CC))[lane];
        acc.x = fmaf(w, hv.x, acc.x); acc.y = fmaf(w, hv.y, acc.y);
        acc.z = fmaf(w, hv.z, acc.z); acc.w = fmaf(w, hv.w, acc.w);
    }
    ((float4*)(g_out + (size_t)gw * CC))[lane] = acc;
}

// ---------------------------------------------------------------------------
// MB accumulate: 4 blocks x 8 warps per codeword; each warp holds a full
// 128-col row (lane = 4 cols), strides the bucket, one red.v4 at the end.
// ---------------------------------------------------------------------------
__global__ void mb_accum_kernel() {
    const int m    = blockIdx.x >> 2;
    const int part = blockIdx.x & 3;
    const int wid  = threadIdx.x >> 5;   // 0..7
    const int lane = threadIdx.x & 31;
    int n = g_ccnt[m]; if (n > CAPM) n = CAPM;

    const int2* ep = g_ment + (size_t)m * CAPM;
    float4 acc = make_float4(0.f, 0.f, 0.f, 0.f);
    const int start = part * 8 + wid;    // 0..31, stride 32

    int e = start;
    int2 nxt = (e < n) ? ep[e] : make_int2(0, 0);
    for (; e < n; e += 32) {
        const int2 cur = nxt;
        if (e + 32 < n) nxt = ep[e + 32];
        const float w = __int_as_float(cur.y);
        const float4 hv = ((const float4*)(g_h + (size_t)cur.x * CC))[lane];
        acc.x = fmaf(w, hv.x, acc.x); acc.y = fmaf(w, hv.y, acc.y);
        acc.z = fmaf(w, hv.z, acc.z); acc.w = fmaf(w, hv.w, acc.w);
    }
    red_add_v4(g_macc + m * CC + lane * 4, acc);
}

// ---------------------------------------------------------------------------
// info_backward = wr * sum_{b,m,e} (macc[m, b*32+e] + b_conv[b*32+e]) * vq[b,m,e]
// ---------------------------------------------------------------------------
__global__ void info_kernel(const float* __restrict__ vq_grad,
                            const float* __restrict__ b_conv,
                            const float* __restrict__ wr_p,
                            float* __restrict__ out_scalar) {
    __shared__ float red[256];
    float s = 0.0f;
    for (int idx = threadIdx.x; idx < NBR * MD; idx += 256) {
        const int b = idx >> 13;
        const int r = idx & (MD - 1);
        const int m = r >> 5;
        const int e = r & 31;
        const int col = b * DD + e;
        s += (g_macc[m * CC + col] + b_conv[col]) * vq_grad[idx];
    }
    red[threadIdx.x] = s;
    __syncthreads();
    for (int st = 128; st > 0; st >>= 1) {
        if (threadIdx.x < st) red[threadIdx.x] += red[threadIdx.x + st];
        __syncthreads();
    }
    if (threadIdx.x == 0) *out_scalar = red[0] * wr_p[0];
}

// ---------------------------------------------------------------------------
// Y[r,c] = sum_k out[r,k]*W_fc[k,c] + b_fc[c] + X_B[r,c]
// ---------------------------------------------------------------------------
__global__ void y_kernel(const float* __restrict__ X,
                         const float* __restrict__ W_fc,
                         const float* __restrict__ b_fc,
                         float* __restrict__ Y) {
    __shared__ float Xs[16][CC];
    const int row0 = blockIdx.x * 16;
    for (int i = threadIdx.x; i < 16 * CC; i += 256) {
        const int r = i >> 7, c = i & 127;
        Xs[r][c] = g_out[(size_t)(row0 + r) * CC + c];
    }
    __syncthreads();

    const int cg = threadIdx.x & 31;
    const int rg = threadIdx.x >> 5;
    const float4* W4 = (const float4*)W_fc;

    float4 acc0 = make_float4(0.f, 0.f, 0.f, 0.f);
    float4 acc1 = make_float4(0.f, 0.f, 0.f, 0.f);

    #pragma unroll 4
    for (int k = 0; k < CC; k++) {
        const float4 wv = W4[k * 32 + cg];
        const float x0 = Xs[rg * 2 + 0][k];
        const float x1 = Xs[rg * 2 + 1][k];
        acc0.x = fmaf(x0, wv.x, acc0.x); acc0.y = fmaf(x0, wv.y, acc0.y);
        acc0.z = fmaf(x0, wv.z, acc0.z); acc0.w = fmaf(x0, wv.w, acc0.w);
        acc1.x = fmaf(x1, wv.x, acc1.x); acc1.y = fmaf(x1, wv.y, acc1.y);
        acc1.z = fmaf(x1, wv.z, acc1.z); acc1.w = fmaf(x1, wv.w, acc1.w);
    }

    const float4 bf = ((const float4*)b_fc)[cg];
    {
        const int row = row0 + rg * 2;
        const float4 xb = ((const float4*)(X + (size_t)row * CC))[cg];
        ((float4*)(Y + (size_t)row * CC))[cg] =
            make_float4(acc0.x + bf.x + xb.x, acc0.y + bf.y + xb.y,
                        acc0.z + bf.z + xb.z, acc0.w + bf.w + xb.w);
    }
    {
        const int row = row0 + rg * 2 + 1;
        const float4 xb = ((const float4*)(X + (size_t)row * CC))[cg];
        ((float4*)(Y + (size_t)row * CC))[cg] =
            make_float4(acc1.x + bf.x + xb.x, acc1.y + bf.y + xb.y,
                        acc1.z + bf.z + xb.z, acc1.w + bf.w + xb.w);
    }
}

// ---------------------------------------------------------------------------
extern "C" void kernel_launch(void* const* d_in, const int* in_sizes, int n_in,
                              void* d_out, int out_size) {
    const float* X_B      = (const float*)d_in[0];
    const int*   esrc_bb  = (const int*)  d_in[1];
    const int*   edst_bb  = (const int*)  d_in[2];
    const float* ew_bb    = (const float*)d_in[3];
    const int*   esrc_bm  = (const int*)  d_in[4];
    const int*   edst_bm  = (const int*)  d_in[5];
    const float* ew_bm    = (const float*)d_in[6];
    const int*   c_idx    = (const int*)  d_in[7];
    const float* wr       = (const float*)d_in[8];
    const float* codebook = (const float*)d_in[9];
    const float* vq_grad  = (const float*)d_in[10];
    const float* W_conv   = (const float*)d_in[11];
    const float* b_conv   = (const float*)d_in[12];
    const float* W_fc     = (const float*)d_in[13];
    const float* b_fc     = (const float*)d_in[14];
    float* out = (float*)d_out;

    const int Ebb  = in_sizes[1];
    const int Ebm  = in_sizes[4];
    const int Etot = Ebb + Ebm;

    // zero counters + macc
    {
        const int total = BN + MM + MM * CC;
        zero_kernel<<<(total + 255) / 256, 256>>>();
    }
    // h = Xin @ blockdiag(W_conv)
    {
        const int warps  = ((NODES + 31) / 32) * NBR;
        compute_h_kernel<<<(warps * 32 + 255) / 256, 256>>>(X_B, codebook, W_conv, wr);
    }
    // bucket edges
    fill_dst_kernel<<<(Etot + 255) / 256, 256>>>(esrc_bb, edst_bb, ew_bb,
                                                 esrc_bm, edst_bm, ew_bm,
                                                 c_idx, Ebb, Etot);
    mb_fill_kernel<<<(Ebm + 256 * EPT - 1) / (256 * EPT), 256>>>(esrc_bm, edst_bm,
                                                                  ew_bm, c_idx, Ebm);
    // aggregate
    gather_kernel<<<(BN * 32 + 255) / 256, 256>>>(b_conv);
    mb_accum_kernel<<<MM * 4, 256>>>();
    // outputs
    info_kernel<<<1, 256>>>(vq_grad, b_conv, wr, out + (out_size - 1));
    y_kernel<<<BN / 16, 256>>>(X_B, W_fc, b_fc, out);
}

// round 4
// speedup vs baseline: 1.6823x; 1.2591x over previous
#include <cuda_runtime.h>
#include <cuda_fp16.h>
#include <cstdint>

#define BN     50000
#define NBR    4
#define DD     32
#define CC     128          // NBR*DD
#define MM     256
#define NODES  (BN + MM)    // 50256
#define CAPR   128          // per-batch-row bucket capacity (mean ~40)

// scratch (static device globals — no allocation)
__device__ __half g_h16[(size_t)NODES * CC];   // 12.9MB (Y path only)
__device__ float  g_out[(size_t)BN * CC];
__device__ int    g_cnt[BN];
__device__ int2   g_ent[(size_t)BN * CAPR];    // (src_row, w_bits) per batch-dst
__device__ float  g_vq32[MM * CC];             // vq_grad re-laid [m][b*32+e], 128KB
__device__ float  g_vsum[(size_t)BN * CC];     // per-row sum w*vq (fp32)
__device__ float  g_info;

// ---------------------------------------------------------------------------
__global__ void zero_kernel() {
    const int idx = blockIdx.x * blockDim.x + threadIdx.x;
    if (idx < BN) g_cnt[idx] = 0;
    if (idx == 0) g_info = 0.0f;
}

// vq_grad [b][m][e] fp32 -> g_vq32 [m][b*32+e] fp32
__global__ void vq_relayout_kernel(const float* __restrict__ vq_grad) {
    const int idx = blockIdx.x * blockDim.x + threadIdx.x;
    if (idx >= NBR * MM * DD) return;
    const int b = idx >> 13;
    const int m = (idx >> 5) & (MM - 1);
    const int e = idx & 31;
    g_vq32[m * CC + b * DD + e] = vq_grad[idx];
}

// ---------------------------------------------------------------------------
// Bucket all edges by destination batch row (bb + bm streams).
// src for bm edges remapped to codeword row BN + c_indices[src].
// ---------------------------------------------------------------------------
__global__ void fill_dst_kernel(const int* __restrict__ sbb, const int* __restrict__ dbb,
                                const float* __restrict__ wbb,
                                const int* __restrict__ sbm, const int* __restrict__ dbm,
                                const float* __restrict__ wbm,
                                const int* __restrict__ cidx, int Ebb, int Etot) {
    const int i = blockIdx.x * blockDim.x + threadIdx.x;
    if (i >= Etot) return;
    int r, s; float w;
    if (i < Ebb) { r = dbb[i]; s = sbb[i]; w = wbb[i]; }
    else { const int j = i - Ebb; r = dbm[j]; s = BN + cidx[sbm[j]]; w = wbm[j]; }
    const int pos = atomicAdd(&g_cnt[r], 1);
    if (pos < CAPR)
        g_ent[(size_t)r * CAPR + pos] = make_int2(s, __float_as_int(w));
}

// ---------------------------------------------------------------------------
// vsum[r] = sum over bucket entries with src >= BN of w * vq32[src-BN].
// Warp per row; vq32 is L1-resident so only entry reads + vsum writes hit L2.
// ---------------------------------------------------------------------------
__global__ void vsum_kernel() {
    const int gw   = (blockIdx.x * blockDim.x + threadIdx.x) >> 5;
    const int lane = threadIdx.x & 31;
    if (gw >= BN) return;
    int n = g_cnt[gw]; if (n > CAPR) n = CAPR;

    float4 vs = make_float4(0.f, 0.f, 0.f, 0.f);
    const int2* ep = g_ent + (size_t)gw * CAPR;
    for (int e = 0; e < n; e++) {
        const int2 E = ep[e];            // warp-uniform broadcast load
        if (E.x >= BN) {
            const float w = __int_as_float(E.y);
            const float4 q = ((const float4*)(g_vq32 + (size_t)(E.x - BN) * CC))[lane];
            vs.x = fmaf(w, q.x, vs.x); vs.y = fmaf(w, q.y, vs.y);
            vs.z = fmaf(w, q.z, vs.z); vs.w = fmaf(w, q.w, vs.w);
        }
    }
    ((float4*)(g_vsum + (size_t)gw * CC))[lane] = vs;
}

// ---------------------------------------------------------------------------
// h16[node, b*32+e] = sum_d Xin[node, b*32+d] * W_conv[b, d, e]   (fp16 store)
// PLUS exact fp32 info partial: dot(h32_row, vsum_row) while h32 is live in
// registers. One warp = (32 rows, 1 branch).
// ---------------------------------------------------------------------------
__global__ void compute_h_kernel(const float* __restrict__ X,
                                 const float* __restrict__ codebook,
                                 const float* __restrict__ W_conv,
                                 const float* __restrict__ wr_p) {
    __shared__ float Ws[NBR * DD * DD];   // 16KB
    for (int i = threadIdx.x; i < NBR * DD * DD; i += blockDim.x)
        Ws[i] = W_conv[i];
    __syncthreads();

    const float wr = wr_p[0];
    const int gw   = (blockIdx.x * blockDim.x + threadIdx.x) >> 5;
    const int lane = threadIdx.x & 31;
    const int b    = gw & 3;
    const int row  = (gw >> 2) * 32 + lane;

    float x[DD];
    bool active = (row < NODES);
    if (active) {
        if (row < BN) {
            const float4* p = (const float4*)(X + (size_t)row * CC + b * DD);
            #pragma unroll
            for (int i = 0; i < 8; i++) {
                float4 v = p[i];
                x[4*i+0] = v.x; x[4*i+1] = v.y; x[4*i+2] = v.z; x[4*i+3] = v.w;
            }
        } else {
            const int m = row - BN;
            const float4* p = (const float4*)(codebook + ((size_t)b * MM + m) * DD);
            #pragma unroll
            for (int i = 0; i < 8; i++) {
                float4 v = p[i];
                x[4*i+0] = v.x * wr; x[4*i+1] = v.y * wr;
                x[4*i+2] = v.z * wr; x[4*i+3] = v.w * wr;
            }
        }
    } else {
        #pragma unroll
        for (int i = 0; i < DD; i++) x[i] = 0.0f;
    }

    float acc[DD];
    #pragma unroll
    for (int e = 0; e < DD; e++) acc[e] = 0.0f;
    #pragma unroll
    for (int d = 0; d < DD; d++) {
        const float xd = x[d];
        const float* wrow = &Ws[b * (DD*DD) + d * DD];
        #pragma unroll
        for (int e = 0; e < DD; e++)
            acc[e] = fmaf(xd, wrow[e], acc[e]);
    }

    // info partial: exact fp32 dot of this h-row-segment with vsum[row] segment
    float p = 0.0f;
    if (active && row < BN) {
        const float4* vp = (const float4*)(g_vsum + (size_t)row * CC + b * DD);
        #pragma unroll
        for (int i = 0; i < 8; i++) {
            const float4 v = vp[i];
            p = fmaf(acc[4*i+0], v.x, p);
            p = fmaf(acc[4*i+1], v.y, p);
            p = fmaf(acc[4*i+2], v.z, p);
            p = fmaf(acc[4*i+3], v.w, p);
        }
    }
    #pragma unroll
    for (int s = 16; s > 0; s >>= 1)
        p += __shfl_xor_sync(0xFFFFFFFF, p, s);
    if (lane == 0 && p != 0.0f) atomicAdd(&g_info, p);

    if (active) {
        // pack to fp16: 32 halfs = 64B = 4 x uint4 per lane
        uint4 pk[4];
        #pragma unroll
        for (int i = 0; i < 4; i++) {
            __half2 h0 = __floats2half2_rn(acc[8*i+0], acc[8*i+1]);
            __half2 h1 = __floats2half2_rn(acc[8*i+2], acc[8*i+3]);
            __half2 h2 = __floats2half2_rn(acc[8*i+4], acc[8*i+5]);
            __half2 h3 = __floats2half2_rn(acc[8*i+6], acc[8*i+7]);
            pk[i].x = *(unsigned*)&h0; pk[i].y = *(unsigned*)&h1;
            pk[i].z = *(unsigned*)&h2; pk[i].w = *(unsigned*)&h3;
        }
        uint4* o = (uint4*)(g_h16 + (size_t)row * CC + b * DD);
        #pragma unroll
        for (int i = 0; i < 4; i++) o[i] = pk[i];
    }
}

// ---------------------------------------------------------------------------
// Gather: one warp per batch row. out[r] = b_conv + sum w * h16[src].
// 2-deep software pipeline; dummy entries have w == 0.
// ---------------------------------------------------------------------------
__device__ __forceinline__ void fma_h16(float4& acc, int2 ent, uint2 hv) {
    const float w = __int_as_float(ent.y);
    const float2 f0 = __half22float2(*(const __half2*)&hv.x);
    const float2 f1 = __half22float2(*(const __half2*)&hv.y);
    acc.x = fmaf(w, f0.x, acc.x); acc.y = fmaf(w, f0.y, acc.y);
    acc.z = fmaf(w, f1.x, acc.z); acc.w = fmaf(w, f1.y, acc.w);
}

__global__ void gather_kernel(const float* __restrict__ b_conv) {
    const int gw   = (blockIdx.x * blockDim.x + threadIdx.x) >> 5;
    const int lane = threadIdx.x & 31;
    if (gw >= BN) return;
    int n = g_cnt[gw]; if (n > CAPR) n = CAPR;

    float4 acc = ((const float4*)b_conv)[lane];
    const int2* ep = g_ent + (size_t)gw * CAPR;
    const int2 Z = make_int2(0, 0);   // w bits == 0.0f

    int2 eA = (n > 0) ? ep[0] : Z;
    int2 eB = (n > 1) ? ep[1] : Z;
    uint2 hA = ((const uint2*)(g_h16 + (size_t)eA.x * CC))[lane];
    uint2 hB = ((const uint2*)(g_h16 + (size_t)eB.x * CC))[lane];

    for (int e = 0; e < n; e += 2) {
        const int2 nA = (e + 2 < n) ? ep[e + 2] : Z;
        const int2 nB = (e + 3 < n) ? ep[e + 3] : Z;
        const uint2 nhA = ((const uint2*)(g_h16 + (size_t)nA.x * CC))[lane];
        const uint2 nhB = ((const uint2*)(g_h16 + (size_t)nB.x * CC))[lane];
        fma_h16(acc, eA, hA);
        fma_h16(acc, eB, hB);
        eA = nA; hA = nhA; eB = nB; hB = nhB;
    }
    ((float4*)(g_out + (size_t)gw * CC))[lane] = acc;
}

// ---------------------------------------------------------------------------
// finalize: out_scalar = (g_info + sum b_conv[col]*vq[b,m,e]) * wr
// ---------------------------------------------------------------------------
__global__ void finalize_kernel(const float* __restrict__ vq_grad,
                                const float* __restrict__ b_conv,
                                const float* __restrict__ wr_p,
                                float* __restrict__ out_scalar) {
    __shared__ float red[256];
    float s = 0.0f;
    for (int idx = threadIdx.x; idx < NBR * MM * DD; idx += 256) {
        const int b = idx >> 13;
        const int e = idx & 31;
        s += b_conv[b * DD + e] * vq_grad[idx];
    }
    red[threadIdx.x] = s;
    __syncthreads();
    for (int st = 128; st > 0; st >>= 1) {
        if (threadIdx.x < st) red[threadIdx.x] += red[threadIdx.x + st];
        __syncthreads();
    }
    if (threadIdx.x == 0) *out_scalar = (red[0] + g_info) * wr_p[0];
}

// ---------------------------------------------------------------------------
// Y[r,c] = sum_k out[r,k]*W_fc[k,c] + b_fc[c] + X_B[r,c]
// ---------------------------------------------------------------------------
__global__ void y_kernel(const float* __restrict__ X,
                         const float* __restrict__ W_fc,
                         const float* __restrict__ b_fc,
                         float* __restrict__ Y) {
    __shared__ float Xs[16][CC];
    const int row0 = blockIdx.x * 16;
    for (int i = threadIdx.x; i < 16 * CC; i += 256) {
        const int r = i >> 7, c = i & 127;
        Xs[r][c] = g_out[(size_t)(row0 + r) * CC + c];
    }
    __syncthreads();

    const int cg = threadIdx.x & 31;
    const int rg = threadIdx.x >> 5;
    const float4* W4 = (const float4*)W_fc;

    float4 acc0 = make_float4(0.f, 0.f, 0.f, 0.f);
    float4 acc1 = make_float4(0.f, 0.f, 0.f, 0.f);

    #pragma unroll 4
    for (int k = 0; k < CC; k++) {
        const float4 wv = W4[k * 32 + cg];
        const float x0 = Xs[rg * 2 + 0][k];
        const float x1 = Xs[rg * 2 + 1][k];
        acc0.x = fmaf(x0, wv.x, acc0.x); acc0.y = fmaf(x0, wv.y, acc0.y);
        acc0.z = fmaf(x0, wv.z, acc0.z); acc0.w = fmaf(x0, wv.w, acc0.w);
        acc1.x = fmaf(x1, wv.x, acc1.x); acc1.y = fmaf(x1, wv.y, acc1.y);
        acc1.z = fmaf(x1, wv.z, acc1.z); acc1.w = fmaf(x1, wv.w, acc1.w);
    }

    const float4 bf = ((const float4*)b_fc)[cg];
    {
        const int row = row0 + rg * 2;
        const float4 xb = ((const float4*)(X + (size_t)row * CC))[cg];
        ((float4*)(Y + (size_t)row * CC))[cg] =
            make_float4(acc0.x + bf.x + xb.x, acc0.y + bf.y + xb.y,
                        acc0.z + bf.z + xb.z, acc0.w + bf.w + xb.w);
    }
    {
        const int row = row0 + rg * 2 + 1;
        const float4 xb = ((const float4*)(X + (size_t)row * CC))[cg];
        ((float4*)(Y + (size_t)row * CC))[cg] =
            make_float4(acc1.x + bf.x + xb.x, acc1.y + bf.y + xb.y,
                        acc1.z + bf.z + xb.z, acc1.w + bf.w + xb.w);
    }
}

// ---------------------------------------------------------------------------
extern "C" void kernel_launch(void* const* d_in, const int* in_sizes, int n_in,
                              void* d_out, int out_size) {
    const float* X_B      = (const float*)d_in[0];
    const int*   esrc_bb  = (const int*)  d_in[1];
    const int*   edst_bb  = (const int*)  d_in[2];
    const float* ew_bb    = (const float*)d_in[3];
    const int*   esrc_bm  = (const int*)  d_in[4];
    const int*   edst_bm  = (const int*)  d_in[5];
    const float* ew_bm    = (const float*)d_in[6];
    const int*   c_idx    = (const int*)  d_in[7];
    const float* wr       = (const float*)d_in[8];
    const float* codebook = (const float*)d_in[9];
    const float* vq_grad  = (const float*)d_in[10];
    const float* W_conv   = (const float*)d_in[11];
    const float* b_conv   = (const float*)d_in[12];
    const float* W_fc     = (const float*)d_in[13];
    const float* b_fc     = (const float*)d_in[14];
    float* out = (float*)d_out;

    const int Ebb  = in_sizes[1];
    const int Ebm  = in_sizes[4];
    const int Etot = Ebb + Ebm;

    zero_kernel<<<(BN + 255) / 256, 256>>>();
    vq_relayout_kernel<<<(NBR * MM * DD + 255) / 256, 256>>>(vq_grad);
    fill_dst_kernel<<<(Etot + 255) / 256, 256>>>(esrc_bb, edst_bb, ew_bb,
                                                 esrc_bm, edst_bm, ew_bm,
                                                 c_idx, Ebb, Etot);
    vsum_kernel<<<(BN * 32 + 255) / 256, 256>>>();
    {
        const int warps = ((NODES + 31) / 32) * NBR;
        compute_h_kernel<<<(warps * 32 + 255) / 256, 256>>>(X_B, codebook, W_conv, wr);
    }
    gather_kernel<<<(BN * 32 + 255) / 256, 256>>>(b_conv);
    finalize_kernel<<<1, 256>>>(vq_grad, b_conv, wr, out + (out_size - 1));
    y_kernel<<<BN / 16, 256>>>(X_B, W_fc, b_fc, out);
}